// round 3
// baseline (speedup 1.0000x reference)
#include <cuda_runtime.h>
#include <math.h>

#define BB 2048
#define SS 512
#define HH 256
#define FF 64
#define G3 (3 * HH)    // 768

// ---------------- scratch ----------------
__device__ float g_logits[BB * SS];    // [B, 512]
__device__ float g_ctx[BB * HH];       // [B, 256]
__device__ float g_gh[BB * G3];        // [B, 768]

// ---------------- shared GEMM tile body ----------------
// C[bm:bm+64, bn:bn+64] = A[64,K] * W[64,K]^T + bias.  BK=16, 256 threads, 4x4 microtile.
template<int KDIM, bool CONCAT>
__device__ __forceinline__ void gemm_tile(float* __restrict__ As,   // [16][68]
                                          float* __restrict__ Ws,   // [16][68]
                                          int bm, int bn,
                                          const float* __restrict__ A0,
                                          const float* __restrict__ A1,
                                          const float* __restrict__ W,
                                          const float* __restrict__ bias,
                                          float* __restrict__ C, int N) {
    const int tid = threadIdx.x;
    const int tx = tid & 15;
    const int ty = tid >> 4;

    float acc[4][4];
#pragma unroll
    for (int i = 0; i < 4; i++)
#pragma unroll
        for (int j = 0; j < 4; j++) acc[i][j] = 0.0f;

    for (int k0 = 0; k0 < KDIM; k0 += 16) {
#pragma unroll
        for (int j = 0; j < 4; j++) {
            int i = tid + 256 * j;
            int r = i >> 4;
            int c = i & 15;
            int k = k0 + c;
            float a;
            if (CONCAT)
                a = (k < 256) ? A0[(size_t)(bm + r) * 256 + k]
                              : A1[(size_t)(bm + r) * 64 + (k - 256)];
            else
                a = A0[(size_t)(bm + r) * KDIM + k];
            As[c * 68 + r] = a;
            Ws[c * 68 + r] = W[(size_t)(bn + r) * KDIM + k];
        }
        __syncthreads();

#pragma unroll
        for (int kk = 0; kk < 16; kk++) {
            float4 a4 = *reinterpret_cast<const float4*>(&As[kk * 68 + ty * 4]);
            float4 w4 = *reinterpret_cast<const float4*>(&Ws[kk * 68 + tx * 4]);
            float av[4] = {a4.x, a4.y, a4.z, a4.w};
            float wv[4] = {w4.x, w4.y, w4.z, w4.w};
#pragma unroll
            for (int i = 0; i < 4; i++)
#pragma unroll
                for (int j = 0; j < 4; j++) acc[i][j] = fmaf(av[i], wv[j], acc[i][j]);
        }
        __syncthreads();
    }

#pragma unroll
    for (int i = 0; i < 4; i++) {
        int m = bm + ty * 4 + i;
#pragma unroll
        for (int j = 0; j < 4; j++) {
            int n = bn + tx * 4 + j;
            C[(size_t)m * N + n] = acc[i][j] + bias[n];
        }
    }
}

// ---------------- K1: logits GEMM (fused concat) + gh GEMM + out init, flat grid ----------------
// blocks [0,256): logits (8 x 32 tiles); [256,640): gh (12 x 32); [640,648): init d_out.
__global__ __launch_bounds__(256)
void k1_gemms(const float* __restrict__ ph, const float* __restrict__ y,
              const float* __restrict__ attn_W, const float* __restrict__ attn_b,
              const float* __restrict__ W_hh, const float* __restrict__ b_hh,
              const float* __restrict__ out_b,
              float* __restrict__ logits, float* __restrict__ gh,
              float* __restrict__ d_out) {
    __shared__ __align__(16) float As[16 * 68];
    __shared__ __align__(16) float Ws[16 * 68];
    const int bid = blockIdx.x;
    if (bid < 256) {
        int bn = (bid & 7) * 64;
        int bm = (bid >> 3) * 64;
        gemm_tile<320, true>(As, Ws, bm, bn, ph, y, attn_W, attn_b, logits, SS);
    } else if (bid < 640) {
        int idx = bid - 256;
        int bn = (idx % 12) * 64;
        int bm = (idx / 12) * 64;
        gemm_tile<256, false>(As, Ws, bm, bn, ph, nullptr, W_hh, b_hh, gh, G3);
    } else {
        int i = (bid - 640) * 256 + threadIdx.x;
        d_out[i] = out_b[0];
    }
}

// ---------------- K2: fused softmax + ctx (float4 streaming) ----------------
__global__ __launch_bounds__(256)
void softmax_ctx_kernel(const float* __restrict__ logits,
                        const float* __restrict__ enc,
                        float* __restrict__ ctx) {
    const int b = blockIdx.x;
    const int t = threadIdx.x;
    __shared__ float w[SS];
    __shared__ float red[8];
    __shared__ __align__(16) float4 part[256];

    float v0 = logits[(size_t)b * SS + t];
    float v1 = logits[(size_t)b * SS + 256 + t];

    float mx = fmaxf(v0, v1);
#pragma unroll
    for (int o = 16; o; o >>= 1) mx = fmaxf(mx, __shfl_xor_sync(0xffffffffu, mx, o));
    if ((t & 31) == 0) red[t >> 5] = mx;
    __syncthreads();
    mx = fmaxf(fmaxf(fmaxf(red[0], red[1]), fmaxf(red[2], red[3])),
               fmaxf(fmaxf(red[4], red[5]), fmaxf(red[6], red[7])));
    __syncthreads();

    float e0 = __expf(v0 - mx);
    float e1 = __expf(v1 - mx);
    w[t] = e0;
    w[t + 256] = e1;

    float sm = e0 + e1;
#pragma unroll
    for (int o = 16; o; o >>= 1) sm += __shfl_xor_sync(0xffffffffu, sm, o);
    if ((t & 31) == 0) red[t >> 5] = sm;
    __syncthreads();
    float inv = 1.0f / (red[0] + red[1] + red[2] + red[3] +
                        red[4] + red[5] + red[6] + red[7]);

    const float4* ep = reinterpret_cast<const float4*>(enc + (size_t)b * SS * HH);
    const int hq = t & 63;
    const int sr = t >> 6;
    float4 acc = make_float4(0.f, 0.f, 0.f, 0.f);

    for (int s0 = 0; s0 < SS; s0 += 32) {
#pragma unroll
        for (int u = 0; u < 8; u++) {
            int row = s0 + u * 4 + sr;
            float4 v = __ldcs(&ep[(size_t)row * 64 + hq]);
            float ww = w[row];
            acc.x = fmaf(ww, v.x, acc.x);
            acc.y = fmaf(ww, v.y, acc.y);
            acc.z = fmaf(ww, v.z, acc.z);
            acc.w = fmaf(ww, v.w, acc.w);
        }
    }

    part[t] = acc;
    __syncthreads();
    if (t < 64) {
        float4 a = part[t], b4 = part[t + 64], c4 = part[t + 128], d4 = part[t + 192];
        float4 r;
        r.x = (a.x + b4.x + c4.x + d4.x) * inv;
        r.y = (a.y + b4.y + c4.y + d4.y) * inv;
        r.z = (a.z + b4.z + c4.z + d4.z) * inv;
        r.w = (a.w + b4.w + c4.w + d4.w) * inv;
        *reinterpret_cast<float4*>(&ctx[(size_t)b * HH + t * 4]) = r;
    }
}

// ---------------- K3: gi GEMM (3 gates, 32x64 tile) + GRU + h_new + out ----------------
// grid(4, 64): x = hidden tile (64 of 256), y = batch tile (32 of 2048). 256 threads.
__global__ __launch_bounds__(256)
void k3_gru_kernel(const float* __restrict__ ctx,
                   const float* __restrict__ W_ih, const float* __restrict__ b_ih,
                   const float* __restrict__ gh,  const float* __restrict__ ph,
                   const float* __restrict__ outW, float* __restrict__ d_out) {
    __shared__ __align__(16) float As[16 * 36];        // ctx tile [k][b] (32 rows)
    __shared__ __align__(16) float Ws[3][16 * 68];     // W_ih tiles per gate [k][h]

    const int bm = blockIdx.y * 32;   // batch base
    const int bh = blockIdx.x * 64;   // hidden base
    const int tid = threadIdx.x;
    const int tx = tid & 15;          // hidden quad
    const int ty = tid >> 4;          // 0..15, each owns 2 batch rows

    float acc[2][4][3];
#pragma unroll
    for (int i = 0; i < 2; i++)
#pragma unroll
        for (int j = 0; j < 4; j++)
#pragma unroll
            for (int g = 0; g < 3; g++) acc[i][j][g] = 0.0f;

    for (int k0 = 0; k0 < HH; k0 += 16) {
#pragma unroll
        for (int j = 0; j < 2; j++) {
            int i = tid + 256 * j;          // 0..511
            int r = i >> 4, c = i & 15;     // r: 0..31
            As[c * 36 + r] = ctx[(size_t)(bm + r) * HH + k0 + c];
        }
#pragma unroll
        for (int j = 0; j < 12; j++) {
            int i = tid + 256 * j;          // 0..3071
            int r = i >> 4, c = i & 15;     // r: 0..191
            int g = r >> 6, rr = r & 63;
            Ws[g][c * 68 + rr] = W_ih[(size_t)(g * HH + bh + rr) * HH + k0 + c];
        }
        __syncthreads();

#pragma unroll
        for (int kk = 0; kk < 16; kk++) {
            float2 a2 = *reinterpret_cast<const float2*>(&As[kk * 36 + ty * 2]);
            float av[2] = {a2.x, a2.y};
#pragma unroll
            for (int g = 0; g < 3; g++) {
                float4 w4 = *reinterpret_cast<const float4*>(&Ws[g][kk * 68 + tx * 4]);
                float wv[4] = {w4.x, w4.y, w4.z, w4.w};
#pragma unroll
                for (int i = 0; i < 2; i++)
#pragma unroll
                    for (int j = 0; j < 4; j++)
                        acc[i][j][g] = fmaf(av[i], wv[j], acc[i][j][g]);
            }
        }
        __syncthreads();
    }

    // epilogue: gates, h_new, out projection
#pragma unroll
    for (int i = 0; i < 2; i++) {
        const int b = bm + ty * 2 + i;
        const float* ghb = gh + (size_t)b * G3;
        float p = 0.0f;
#pragma unroll
        for (int j = 0; j < 4; j++) {
            const int h = bh + tx * 4 + j;
            float gir = acc[i][j][0] + b_ih[h];
            float giz = acc[i][j][1] + b_ih[h + 256];
            float gin = acc[i][j][2] + b_ih[h + 512];
            float r = 1.0f / (1.0f + __expf(-(gir + ghb[h])));
            float z = 1.0f / (1.0f + __expf(-(giz + ghb[h + 256])));
            float n = tanhf(gin + r * ghb[h + 512]);
            float hv = (1.0f - z) * n + z * ph[(size_t)b * HH + h];
            d_out[BB + (size_t)b * HH + h] = hv;
            p = fmaf(hv, outW[h], p);
        }
        // reduce across the 16 tx lanes (same ty, same warp half)
        p += __shfl_xor_sync(0xffffffffu, p, 1);
        p += __shfl_xor_sync(0xffffffffu, p, 2);
        p += __shfl_xor_sync(0xffffffffu, p, 4);
        p += __shfl_xor_sync(0xffffffffu, p, 8);
        if (tx == 0) atomicAdd(&d_out[b], p);
    }
}

// ---------------- launcher ----------------
extern "C" void kernel_launch(void* const* d_in, const int* in_sizes, int n_in,
                              void* d_out, int out_size) {
    const float* enc    = (const float*)d_in[0];
    const float* ph     = (const float*)d_in[1];
    const float* y      = (const float*)d_in[2];
    const float* attn_W = (const float*)d_in[3];
    const float* attn_b = (const float*)d_in[4];
    const float* W_ih   = (const float*)d_in[5];
    const float* W_hh   = (const float*)d_in[6];
    const float* b_ih   = (const float*)d_in[7];
    const float* b_hh   = (const float*)d_in[8];
    const float* out_W  = (const float*)d_in[9];
    const float* out_b  = (const float*)d_in[10];
    float* out = (float*)d_out;

    float *logits = nullptr, *ctx = nullptr, *gh = nullptr;
    cudaGetSymbolAddress((void**)&logits, g_logits);
    cudaGetSymbolAddress((void**)&ctx,    g_ctx);
    cudaGetSymbolAddress((void**)&gh,     g_gh);

    k1_gemms<<<648, 256>>>(ph, y, attn_W, attn_b, W_hh, b_hh, out_b, logits, gh, out);
    softmax_ctx_kernel<<<BB, 256>>>(logits, enc, ctx);
    k3_gru_kernel<<<dim3(4, 64), 256>>>(ctx, W_ih, b_ih, gh, ph, out_W, out);
}

// round 4
// speedup vs baseline: 1.1035x; 1.1035x over previous
#include <cuda_runtime.h>
#include <math.h>

#define BB 2048
#define SS 512
#define HH 256
#define FF 64
#define G3 (3 * HH)    // 768

// ---------------- scratch ----------------
__device__ float g_logits[BB * SS];    // [B, 512]
__device__ float g_ctx[BB * HH];       // [B, 256]
__device__ float g_gh[BB * G3];        // [B, 768]

// ---------------- shared GEMM tile body ----------------
// C[bm:bm+64, bn:bn+64] = A[64,K] * W[64,K]^T + bias.  BK=16, 256 threads, 4x4 microtile.
template<int KDIM, bool CONCAT>
__device__ __forceinline__ void gemm_tile(float* __restrict__ As,   // [16][68]
                                          float* __restrict__ Ws,   // [16][68]
                                          int bm, int bn,
                                          const float* __restrict__ A0,
                                          const float* __restrict__ A1,
                                          const float* __restrict__ W,
                                          const float* __restrict__ bias,
                                          float* __restrict__ C, int N) {
    const int tid = threadIdx.x;
    const int tx = tid & 15;
    const int ty = tid >> 4;

    float acc[4][4];
#pragma unroll
    for (int i = 0; i < 4; i++)
#pragma unroll
        for (int j = 0; j < 4; j++) acc[i][j] = 0.0f;

    for (int k0 = 0; k0 < KDIM; k0 += 16) {
#pragma unroll
        for (int j = 0; j < 4; j++) {
            int i = tid + 256 * j;
            int r = i >> 4;
            int c = i & 15;
            int k = k0 + c;
            float a;
            if (CONCAT)
                a = (k < 256) ? A0[(size_t)(bm + r) * 256 + k]
                              : A1[(size_t)(bm + r) * 64 + (k - 256)];
            else
                a = A0[(size_t)(bm + r) * KDIM + k];
            As[c * 68 + r] = a;
            Ws[c * 68 + r] = W[(size_t)(bn + r) * KDIM + k];
        }
        __syncthreads();

#pragma unroll
        for (int kk = 0; kk < 16; kk++) {
            float4 a4 = *reinterpret_cast<const float4*>(&As[kk * 68 + ty * 4]);
            float4 w4 = *reinterpret_cast<const float4*>(&Ws[kk * 68 + tx * 4]);
            float av[4] = {a4.x, a4.y, a4.z, a4.w};
            float wv[4] = {w4.x, w4.y, w4.z, w4.w};
#pragma unroll
            for (int i = 0; i < 4; i++)
#pragma unroll
                for (int j = 0; j < 4; j++) acc[i][j] = fmaf(av[i], wv[j], acc[i][j]);
        }
        __syncthreads();
    }

#pragma unroll
    for (int i = 0; i < 4; i++) {
        int m = bm + ty * 4 + i;
#pragma unroll
        for (int j = 0; j < 4; j++) {
            int n = bn + tx * 4 + j;
            C[(size_t)m * N + n] = acc[i][j] + bias[n];
        }
    }
}

// ---------------- K1: logits GEMM only (fused concat), 256 blocks ----------------
__global__ __launch_bounds__(256)
void k1_logits(const float* __restrict__ ph, const float* __restrict__ y,
               const float* __restrict__ attn_W, const float* __restrict__ attn_b,
               float* __restrict__ logits) {
    __shared__ __align__(16) float As[16 * 68];
    __shared__ __align__(16) float Ws[16 * 68];
    int bn = (blockIdx.x & 7) * 64;
    int bm = (blockIdx.x >> 3) * 64;
    gemm_tile<320, true>(As, Ws, bm, bn, ph, y, attn_W, attn_b, logits, SS);
}

// ---------------- K2: gh-GEMM (compute) overlapped with softmax+ctx (HBM stream) ----------------
// blocks [0,384): gh GEMM; [384,392): init d_out; [392, 392+2048): softmax_ctx.
union SmemK2 {
    struct { float As[16 * 68]; float Ws[16 * 68]; } gemm;
    struct { float w[SS]; float red[8]; float4 part[256]; } sm;
};

__device__ __forceinline__ void softmax_ctx_body(SmemK2& s, int b,
                                                 const float* __restrict__ logits,
                                                 const float* __restrict__ enc,
                                                 float* __restrict__ ctx) {
    const int t = threadIdx.x;

    float v0 = logits[(size_t)b * SS + t];
    float v1 = logits[(size_t)b * SS + 256 + t];

    float mx = fmaxf(v0, v1);
#pragma unroll
    for (int o = 16; o; o >>= 1) mx = fmaxf(mx, __shfl_xor_sync(0xffffffffu, mx, o));
    if ((t & 31) == 0) s.sm.red[t >> 5] = mx;
    __syncthreads();
    mx = fmaxf(fmaxf(fmaxf(s.sm.red[0], s.sm.red[1]), fmaxf(s.sm.red[2], s.sm.red[3])),
               fmaxf(fmaxf(s.sm.red[4], s.sm.red[5]), fmaxf(s.sm.red[6], s.sm.red[7])));
    __syncthreads();

    float e0 = __expf(v0 - mx);
    float e1 = __expf(v1 - mx);
    s.sm.w[t] = e0;
    s.sm.w[t + 256] = e1;

    float smv = e0 + e1;
#pragma unroll
    for (int o = 16; o; o >>= 1) smv += __shfl_xor_sync(0xffffffffu, smv, o);
    if ((t & 31) == 0) s.sm.red[t >> 5] = smv;
    __syncthreads();
    float inv = 1.0f / (s.sm.red[0] + s.sm.red[1] + s.sm.red[2] + s.sm.red[3] +
                        s.sm.red[4] + s.sm.red[5] + s.sm.red[6] + s.sm.red[7]);

    const float4* ep = reinterpret_cast<const float4*>(enc + (size_t)b * SS * HH);
    const int hq = t & 63;
    const int sr = t >> 6;
    float4 acc = make_float4(0.f, 0.f, 0.f, 0.f);

    for (int s0 = 0; s0 < SS; s0 += 32) {
#pragma unroll
        for (int u = 0; u < 8; u++) {
            int row = s0 + u * 4 + sr;
            float4 v = __ldcs(&ep[(size_t)row * 64 + hq]);
            float ww = s.sm.w[row];
            acc.x = fmaf(ww, v.x, acc.x);
            acc.y = fmaf(ww, v.y, acc.y);
            acc.z = fmaf(ww, v.z, acc.z);
            acc.w = fmaf(ww, v.w, acc.w);
        }
    }

    s.sm.part[t] = acc;
    __syncthreads();
    if (t < 64) {
        float4 a = s.sm.part[t], b4 = s.sm.part[t + 64];
        float4 c4 = s.sm.part[t + 128], d4 = s.sm.part[t + 192];
        float4 r;
        r.x = (a.x + b4.x + c4.x + d4.x) * inv;
        r.y = (a.y + b4.y + c4.y + d4.y) * inv;
        r.z = (a.z + b4.z + c4.z + d4.z) * inv;
        r.w = (a.w + b4.w + c4.w + d4.w) * inv;
        *reinterpret_cast<float4*>(&ctx[(size_t)b * HH + t * 4]) = r;
    }
}

__global__ __launch_bounds__(256)
void k2_stream_gemm(const float* __restrict__ logits, const float* __restrict__ enc,
                    const float* __restrict__ ph,
                    const float* __restrict__ W_hh, const float* __restrict__ b_hh,
                    const float* __restrict__ out_b,
                    float* __restrict__ ctx, float* __restrict__ gh,
                    float* __restrict__ d_out) {
    __shared__ __align__(16) SmemK2 s;
    const int bid = blockIdx.x;
    if (bid < 384) {
        int bn = (bid % 12) * 64;
        int bm = (bid / 12) * 64;
        gemm_tile<256, false>(s.gemm.As, s.gemm.Ws, bm, bn, ph, nullptr, W_hh, b_hh, gh, G3);
    } else if (bid < 392) {
        int i = (bid - 384) * 256 + threadIdx.x;
        d_out[i] = out_b[0];
    } else {
        softmax_ctx_body(s, bid - 392, logits, enc, ctx);
    }
}

// ---------------- K3: gi GEMM (3 gates, 32x64 tile) + GRU + h_new + out ----------------
__global__ __launch_bounds__(256)
void k3_gru_kernel(const float* __restrict__ ctx,
                   const float* __restrict__ W_ih, const float* __restrict__ b_ih,
                   const float* __restrict__ gh,  const float* __restrict__ ph,
                   const float* __restrict__ outW, float* __restrict__ d_out) {
    __shared__ __align__(16) float As[16 * 36];
    __shared__ __align__(16) float Ws[3][16 * 68];

    const int bm = blockIdx.y * 32;
    const int bh = blockIdx.x * 64;
    const int tid = threadIdx.x;
    const int tx = tid & 15;
    const int ty = tid >> 4;

    float acc[2][4][3];
#pragma unroll
    for (int i = 0; i < 2; i++)
#pragma unroll
        for (int j = 0; j < 4; j++)
#pragma unroll
            for (int g = 0; g < 3; g++) acc[i][j][g] = 0.0f;

    for (int k0 = 0; k0 < HH; k0 += 16) {
#pragma unroll
        for (int j = 0; j < 2; j++) {
            int i = tid + 256 * j;
            int r = i >> 4, c = i & 15;
            As[c * 36 + r] = ctx[(size_t)(bm + r) * HH + k0 + c];
        }
#pragma unroll
        for (int j = 0; j < 12; j++) {
            int i = tid + 256 * j;
            int r = i >> 4, c = i & 15;
            int g = r >> 6, rr = r & 63;
            Ws[g][c * 68 + rr] = W_ih[(size_t)(g * HH + bh + rr) * HH + k0 + c];
        }
        __syncthreads();

#pragma unroll
        for (int kk = 0; kk < 16; kk++) {
            float2 a2 = *reinterpret_cast<const float2*>(&As[kk * 36 + ty * 2]);
            float av[2] = {a2.x, a2.y};
#pragma unroll
            for (int g = 0; g < 3; g++) {
                float4 w4 = *reinterpret_cast<const float4*>(&Ws[g][kk * 68 + tx * 4]);
                float wv[4] = {w4.x, w4.y, w4.z, w4.w};
#pragma unroll
                for (int i = 0; i < 2; i++)
#pragma unroll
                    for (int j = 0; j < 4; j++)
                        acc[i][j][g] = fmaf(av[i], wv[j], acc[i][j][g]);
            }
        }
        __syncthreads();
    }

#pragma unroll
    for (int i = 0; i < 2; i++) {
        const int b = bm + ty * 2 + i;
        const float* ghb = gh + (size_t)b * G3;
        float p = 0.0f;
#pragma unroll
        for (int j = 0; j < 4; j++) {
            const int h = bh + tx * 4 + j;
            float gir = acc[i][j][0] + b_ih[h];
            float giz = acc[i][j][1] + b_ih[h + 256];
            float gin = acc[i][j][2] + b_ih[h + 512];
            float r = 1.0f / (1.0f + __expf(-(gir + ghb[h])));
            float z = 1.0f / (1.0f + __expf(-(giz + ghb[h + 256])));
            float n = tanhf(gin + r * ghb[h + 512]);
            float hv = (1.0f - z) * n + z * ph[(size_t)b * HH + h];
            d_out[BB + (size_t)b * HH + h] = hv;
            p = fmaf(hv, outW[h], p);
        }
        p += __shfl_xor_sync(0xffffffffu, p, 1);
        p += __shfl_xor_sync(0xffffffffu, p, 2);
        p += __shfl_xor_sync(0xffffffffu, p, 4);
        p += __shfl_xor_sync(0xffffffffu, p, 8);
        if (tx == 0) atomicAdd(&d_out[b], p);
    }
}

// ---------------- launcher ----------------
extern "C" void kernel_launch(void* const* d_in, const int* in_sizes, int n_in,
                              void* d_out, int out_size) {
    const float* enc    = (const float*)d_in[0];
    const float* ph     = (const float*)d_in[1];
    const float* y      = (const float*)d_in[2];
    const float* attn_W = (const float*)d_in[3];
    const float* attn_b = (const float*)d_in[4];
    const float* W_ih   = (const float*)d_in[5];
    const float* W_hh   = (const float*)d_in[6];
    const float* b_ih   = (const float*)d_in[7];
    const float* b_hh   = (const float*)d_in[8];
    const float* out_W  = (const float*)d_in[9];
    const float* out_b  = (const float*)d_in[10];
    float* out = (float*)d_out;

    float *logits = nullptr, *ctx = nullptr, *gh = nullptr;
    cudaGetSymbolAddress((void**)&logits, g_logits);
    cudaGetSymbolAddress((void**)&ctx,    g_ctx);
    cudaGetSymbolAddress((void**)&gh,     g_gh);

    k1_logits<<<256, 256>>>(ph, y, attn_W, attn_b, logits);
    k2_stream_gemm<<<392 + BB, 256>>>(logits, enc, ph, W_hh, b_hh, out_b, ctx, gh, out);
    k3_gru_kernel<<<dim3(4, 64), 256>>>(ctx, W_ih, b_ih, gh, ph, out_W, out);
}